// round 16
// baseline (speedup 1.0000x reference)
#include <cuda_runtime.h>
#include <cuda_bf16.h>

#define TENC 48
#define TDEC 24
#define DSTEPS 30
#define HD 128
#define NF1 17
#define NF2 129
#define KP1 160       // [h(128) | x(17) pad->32]
#define KP2 272       // [h(128) | x(129) pad->144]
#define KPD 256       // [h(128) | din(128)]
#define XH1 8
#define XH2 36
#define G 8
#define NCTA 128
#define NTH 512
#define NG 512
#define BTOT 1024
#define HCT_STR 10

typedef unsigned long long u64;

// ---------------- device scratch (allocation-free) ----------------
__device__ unsigned g_W21[(KP1 / 2) * NG];   // [row][n], row=k-pair, order [h|x]
__device__ unsigned g_W22[(KP2 / 2) * NG];
__device__ unsigned g_W2d[(KPD / 2) * NG];   // decoder: order [h|din]
__device__ float g_Wet1[256 * TENC];
__device__ float g_Wet2[256 * TENC];
__device__ float g_Wdt[256 * HD];
__device__ float g_Udt[HD * HD];
__device__ float g_b1[NG], g_b2[NG], g_bd[NG];
__device__ float g_pre1[BTOT * TENC * NF1];           // [b][s][f] fp32
__device__ __nv_bfloat16 g_pre2h[BTOT * TENC * NF2];  // [b][s][f] bf16
__device__ float g_mid[BTOT * TENC * NF2];
__device__ float g_fin[BTOT * TENC * HD];
__device__ __nv_bfloat16 g_udTh[BTOT * HD * TENC];

// ---------------- math helpers ----------------
__device__ __forceinline__ float tanha(float x) {
    float y; asm("tanh.approx.f32 %0, %1;" : "=f"(y) : "f"(x)); return y;
}
__device__ __forceinline__ float siga(float x) {
    return fmaf(tanha(0.5f * x), 0.5f, 0.5f);
}
__device__ __forceinline__ u64 fma2(u64 a, u64 b, u64 c) {
    u64 d; asm("fma.rn.f32x2 %0, %1, %2, %3;" : "=l"(d) : "l"(a), "l"(b), "l"(c)); return d;
}
__device__ __forceinline__ u64 dup2(float x) {
    u64 d; unsigned r = __float_as_uint(x);
    asm("mov.b64 %0, {%1, %1};" : "=l"(d) : "r"(r)); return d;
}
__device__ __forceinline__ float2 unpack2(u64 a) {
    unsigned l, h;
    asm("mov.b64 {%0, %1}, %2;" : "=r"(l), "=r"(h) : "l"(a));
    return make_float2(__uint_as_float(l), __uint_as_float(h));
}
__device__ __forceinline__ u64 bf2f2(unsigned w) {
    unsigned lo = w << 16;
    unsigned hi = w & 0xffff0000u;
    u64 d;
    asm("mov.b64 %0, {%1, %2};" : "=l"(d) : "r"(lo), "r"(hi));
    return d;
}
__device__ __forceinline__ void barh() {   // lower-half barrier
    asm volatile("bar.sync 1, 256;" ::: "memory");
}

__device__ __forceinline__ void warp_softmax(const float* score_row, float* alpha_row,
                                             int F, int lane) {
    float mx = -1e30f;
    for (int f = lane; f < F; f += 32) mx = fmaxf(mx, score_row[f]);
#pragma unroll
    for (int o = 16; o; o >>= 1) mx = fmaxf(mx, __shfl_xor_sync(0xffffffffu, mx, o));
    float sm = 0.f;
    for (int f = lane; f < F; f += 32) {
        float e = __expf(score_row[f] - mx);
        alpha_row[f] = e;
        sm += e;
    }
#pragma unroll
    for (int o = 16; o; o >>= 1) sm += __shfl_xor_sync(0xffffffffu, sm, o);
    float inv = __fdividef(1.f, sm);
    for (int f = lane; f < F; f += 32) alpha_row[f] *= inv;
}

__global__ void nop_kernel() {}

// ---- partial gate GEMM over u32-row range [r0, r0+NR): 2 cols/thread ----
template <int KP, int NR>
__device__ __forceinline__ void gemm_rows(const unsigned* __restrict__ W2, int r0,
                                          const float* __restrict__ ipT,   // [g][KP]
                                          int lt, u64* acc0, u64* acc1) {
    const u64* wp = (const u64*)(W2 + (size_t)r0 * NG) + lt;
    const float* ipb = ipT + 2 * r0;
#pragma unroll 1
    for (int b = 0; b < NR; b += 4) {
        u64 w4[4];
#pragma unroll
        for (int i = 0; i < 4; i++) w4[i] = wp[(size_t)(b + i) * (NG / 2)];
        u64 wn0[4], wn1[4];
#pragma unroll
        for (int i = 0; i < 4; i++) {
            wn0[i] = bf2f2((unsigned)w4[i]);
            wn1[i] = bf2f2((unsigned)(w4[i] >> 32));
        }
        const float* ipk = ipb + 2 * b;
#pragma unroll
        for (int g = 0; g < 8; g++) {
            const float* r = ipk + g * KP;
            ulonglong2 pA = *(const ulonglong2*)(r);
            ulonglong2 pB = *(const ulonglong2*)(r + 4);
            acc0[g] = fma2(wn0[0], pA.x, acc0[g]);
            acc0[g] = fma2(wn0[1], pA.y, acc0[g]);
            acc0[g] = fma2(wn0[2], pB.x, acc0[g]);
            acc0[g] = fma2(wn0[3], pB.y, acc0[g]);
            acc1[g] = fma2(wn1[0], pA.x, acc1[g]);
            acc1[g] = fma2(wn1[1], pA.y, acc1[g]);
            acc1[g] = fma2(wn1[2], pB.x, acc1[g]);
            acc1[g] = fma2(wn1[3], pB.y, acc1[g]);
        }
    }
}

// ---------------- setup ----------------
__global__ void setup_kernel(
    const float* __restrict__ e1_Wih, const float* __restrict__ e1_Whh,
    const float* __restrict__ e2_Wih, const float* __restrict__ e2_Whh,
    const float* __restrict__ d_Wih,  const float* __restrict__ d_Whh,
    const float* __restrict__ We1,    const float* __restrict__ We2,
    const float* __restrict__ Wd,     const float* __restrict__ Ud,
    const float* __restrict__ e1_bih, const float* __restrict__ e1_bhh,
    const float* __restrict__ e2_bih, const float* __restrict__ e2_bhh,
    const float* __restrict__ d_bih,  const float* __restrict__ d_bhh) {
    int tid = blockIdx.x * blockDim.x + threadIdx.x;
    int nt = gridDim.x * blockDim.x;
    for (int i = tid; i < (KP1 / 2) * NG; i += nt) {
        int kk = i / NG, n = i % NG;
        float v[2];
#pragma unroll
        for (int q = 0; q < 2; q++) {
            int k = 2 * kk + q;
            if (k < HD) v[q] = e1_Whh[n * HD + k];
            else if (k - HD < NF1) v[q] = e1_Wih[n * NF1 + (k - HD)];
            else v[q] = 0.f;
        }
        g_W21[i] = (unsigned)__bfloat16_as_ushort(__float2bfloat16(v[0]))
                 | ((unsigned)__bfloat16_as_ushort(__float2bfloat16(v[1])) << 16);
    }
    for (int i = tid; i < (KP2 / 2) * NG; i += nt) {
        int kk = i / NG, n = i % NG;
        float v[2];
#pragma unroll
        for (int q = 0; q < 2; q++) {
            int k = 2 * kk + q;
            if (k < HD) v[q] = e2_Whh[n * HD + k];
            else if (k - HD < NF2) v[q] = e2_Wih[n * NF2 + (k - HD)];
            else v[q] = 0.f;
        }
        g_W22[i] = (unsigned)__bfloat16_as_ushort(__float2bfloat16(v[0]))
                 | ((unsigned)__bfloat16_as_ushort(__float2bfloat16(v[1])) << 16);
    }
    // decoder: [h(128) | din(128)]
    for (int i = tid; i < (KPD / 2) * NG; i += nt) {
        int kk = i / NG, n = i % NG;
        float v[2];
#pragma unroll
        for (int q = 0; q < 2; q++) {
            int k = 2 * kk + q;
            v[q] = (k < HD) ? d_Whh[n * HD + k] : d_Wih[n * HD + (k - HD)];
        }
        g_W2d[i] = (unsigned)__bfloat16_as_ushort(__float2bfloat16(v[0]))
                 | ((unsigned)__bfloat16_as_ushort(__float2bfloat16(v[1])) << 16);
    }
    for (int i = tid; i < 256 * TENC; i += nt) {
        int k = i / TENC, ss = i % TENC;
        g_Wet1[i] = We1[ss * 256 + k];
        g_Wet2[i] = We2[ss * 256 + k];
    }
    for (int i = tid; i < 256 * HD; i += nt) {
        int k = i / HD, j = i % HD;
        g_Wdt[i] = Wd[j * 256 + k];
    }
    for (int i = tid; i < HD * HD; i += nt) {
        int k = i / HD, j = i % HD;
        g_Udt[i] = Ud[j * HD + k];
    }
    for (int i = tid; i < NG; i += nt) {
        g_b1[i] = e1_bih[i] + e1_bhh[i];
        g_b2[i] = e2_bih[i] + e2_bhh[i];
        g_bd[i] = d_bih[i] + d_bhh[i];
    }
}

// ---------------- pre1 ----------------
__global__ __launch_bounds__(256) void pre1_kernel(
    const float* __restrict__ inp, const float* __restrict__ lab,
    const float* __restrict__ Ue1, const float* __restrict__ Ue1b) {
    __shared__ float xs[TENC * NF1];
    __shared__ float ue[TENC * TENC];
    int b = blockIdx.x, tid = threadIdx.x;
    for (int i = tid; i < TENC * NF1; i += 256) {
        int t = i / NF1, f = i % NF1;
        xs[i] = inp[((size_t)b * TENC + t) * 18 + f + 1];
    }
    for (int i = tid; i < TENC * TENC; i += 256) ue[i] = Ue1[i];
    for (int i = tid; i < TENC; i += 256)
        g_mid[((size_t)b * TENC + i) * NF2 + HD] = lab[(size_t)b * TENC + i];
    __syncthreads();
    for (int i = tid; i < TENC * NF1; i += 256) {
        int ss = i / NF1, f = i % NF1;
        float a = 0.f;
#pragma unroll 8
        for (int t = 0; t < TENC; t++) a += xs[t * NF1 + f] * ue[ss * TENC + t];
        g_pre1[(size_t)b * TENC * NF1 + i] = a + Ue1b[ss];
    }
}

// ---------------- pre2 (bf16 out) ----------------
__global__ __launch_bounds__(256) void pre2_kernel(
    const float* __restrict__ Ue2, const float* __restrict__ Ue2b) {
    __shared__ float ms[TENC * 130];
    __shared__ float ue[TENC * TENC];
    int b = blockIdx.x, tid = threadIdx.x;
    for (int i = tid; i < TENC * NF2; i += 256) {
        int t = i / NF2, f = i % NF2;
        ms[t * 130 + f] = g_mid[(size_t)b * TENC * NF2 + i];
    }
    for (int i = tid; i < TENC; i += 256) ms[i * 130 + 129] = 0.f;
    for (int i = tid; i < TENC * TENC; i += 256) ue[i] = Ue2[i];
    __syncthreads();
    for (int u = tid; u < TENC * 65; u += 256) {
        int ss = u / 65, q = u % 65;
        int f0 = 2 * q;
        u64 acc = 0ull;
#pragma unroll 8
        for (int t = 0; t < TENC; t++)
            acc = fma2(dup2(ue[ss * TENC + t]), *(const u64*)(ms + t * 130 + f0), acc);
        float2 r = unpack2(acc);
        float bb = Ue2b[ss];
        size_t base = (size_t)b * TENC * NF2 + ss * NF2;
        g_pre2h[base + f0] = __float2bfloat16(r.x + bb);
        if (f0 < 128) g_pre2h[base + f0 + 1] = __float2bfloat16(r.y + bb);
    }
}

// ---------------- ud (bf16 out, transposed) ----------------
__global__ __launch_bounds__(256) void ud_kernel(const float* __restrict__ Udb) {
    extern __shared__ float sm_ud[];
    float* udt = sm_ud;
    float* fs  = sm_ud + 16384;
    int b = blockIdx.x, tid = threadIdx.x;
    for (int i = tid; i < HD * HD; i += 256) udt[i] = g_Udt[i];
    for (int i = tid; i < TENC * HD; i += 256) {
        int t = i >> 7, k = i & 127;
        fs[t * 129 + k] = g_fin[(size_t)b * TENC * HD + i];
    }
    __syncthreads();
    for (int u = tid; u < 32 * TENC; u += 256) {
        int t = u % TENC, jq = u / TENC;
        int j0 = 4 * jq;
        float a0 = Udb[j0], a1 = Udb[j0 + 1], a2 = Udb[j0 + 2], a3 = Udb[j0 + 3];
#pragma unroll 8
        for (int k = 0; k < HD; k++) {
            float f = fs[t * 129 + k];
            float4 uu = *(const float4*)(udt + k * HD + j0);
            a0 += f * uu.x; a1 += f * uu.y; a2 += f * uu.z; a3 += f * uu.w;
        }
        size_t base = (size_t)b * HD * TENC;
        g_udTh[base + (size_t)(j0 + 0) * TENC + t] = __float2bfloat16(a0);
        g_udTh[base + (size_t)(j0 + 1) * TENC + t] = __float2bfloat16(a1);
        g_udTh[base + (size_t)(j0 + 2) * TENC + t] = __float2bfloat16(a2);
        g_udTh[base + (size_t)(j0 + 3) * TENC + t] = __float2bfloat16(a3);
    }
}

// ---------------- encoder stage (round-15 verbatim) ----------------
template <int KP, int NF, int XH, bool PB16>
__global__ __launch_bounds__(NTH, 1) void stage_kernel(
    const float* __restrict__ inp,
    const float* __restrict__ Ve, const float* __restrict__ Veb,
    const unsigned* __restrict__ W2, const float* __restrict__ bsum,
    const float* __restrict__ Wet, const float* __restrict__ preF,
    float* __restrict__ outb, int ostride) {
    extern __shared__ float sm[];
    constexpr int PRE_FL = PB16 ? (G * TENC * NF / 2) : (G * TENC * NF);
    constexpr int XS_FL  = PB16 ? 0 : (G * TENC * NF1);
    constexpr int O_PRE = 12288;
    constexpr int O_XS  = O_PRE + PRE_FL;
    constexpr int O_HCT = O_XS + XS_FL;
    constexpr int O_WE  = O_HCT + 256 * HCT_STR;
    constexpr int O_SC  = O_WE + 384;
    constexpr int O_AL  = O_SC + 1056;
    constexpr int O_IP  = O_AL + 1056;
    constexpr int O_GT  = O_IP + KP * 8;
    constexpr int O_PG  = O_GT + 4096;
    constexpr int O_BS  = O_PG + 4608;
    constexpr int O_VV  = O_BS + 512;

    float* wet  = sm;
    float* pres = sm + O_PRE;
    float* xs   = sm + O_XS;
    float* hcT  = sm + O_HCT;
    float* we   = sm + O_WE;
    float* sc   = sm + O_SC;
    float* al   = sm + O_AL;
    float* ipT  = sm + O_IP;
    float* gates = sm + O_GT;
    float* pg   = sm + O_PG;
    float* bias = sm + O_BS;
    float* vvec = sm + O_VV;

    const int tid = threadIdx.x, bid = blockIdx.x;
    const int lower = (tid < 256);
    const int lt = tid & 255;
    const int lw = lt >> 5;
    const int lane = tid & 31;

    for (int i = tid; i < 256 * TENC; i += NTH) wet[i] = Wet[i];
    if (PB16) {
        const unsigned* src = (const unsigned*)(g_pre2h + (size_t)bid * G * TENC * NF2);
        unsigned* dst = (unsigned*)pres;
        for (int i = tid; i < G * TENC * NF2 / 2; i += NTH) dst[i] = src[i];
    } else {
        const float* src = preF + (size_t)bid * G * TENC * NF;
        for (int i = tid; i < G * TENC * NF; i += NTH) pres[i] = src[i];
        for (int i = tid; i < G * TENC * NF1; i += NTH) {
            int g = i / (TENC * NF1);
            int r = i - g * TENC * NF1;
            int t = r / NF1, f = r - t * NF1;
            xs[i] = inp[((size_t)(bid * G + g) * TENC + t) * 18 + f + 1];
        }
    }
    for (int i = tid; i < 256 * HCT_STR; i += NTH) hcT[i] = 0.f;
    for (int i = tid; i < NG; i += NTH) bias[i] = bsum[i];
    for (int i = tid; i < TENC; i += NTH) vvec[i] = Ve[i];
    if (tid == 0) vvec[130] = Veb[0];
    for (int i = tid; i < KP * 8; i += NTH) ipT[i] = 0.f;
    __syncthreads();

    const int ae = lt / 24;
    const int ass0 = 2 * (lt % 24);

    for (int t = 0; t < TENC; t++) {
        if (lower) {
            float xr0 = 0.f, xr1 = 0.f, xr2 = 0.f, xr3 = 0.f, xr4 = 0.f;
            if (PB16) {
                const float* xp = g_mid + ((size_t)(bid * G + lw) * TENC + t) * NF2;
                xr0 = xp[lane]; xr1 = xp[lane + 32];
                xr2 = xp[lane + 64]; xr3 = xp[lane + 96];
                if (lane == 0) xr4 = xp[128];
            } else {
                if (lane < NF) xr0 = xs[lw * TENC * NF1 + t * NF1 + lane];
            }
            if (lt < 192) {
                u64 acc0 = 0ull, acc1 = 0ull;
#pragma unroll 4
                for (int kk = 0; kk < 128; kk++) {
                    u64 w0 = *(const u64*)(wet + kk * TENC + ass0);
                    u64 w1 = *(const u64*)(wet + (kk + 128) * TENC + ass0);
                    acc0 = fma2(w0, dup2(hcT[kk * HCT_STR + ae]), acc0);
                    acc1 = fma2(w1, dup2(hcT[(kk + 128) * HCT_STR + ae]), acc1);
                }
                float2 v0 = unpack2(acc0);
                float2 v1 = unpack2(acc1);
                we[ae * 48 + ass0]     = v0.x + v1.x;
                we[ae * 48 + ass0 + 1] = v0.y + v1.y;
            }
            barh();
            {
                float bb = vvec[130];
                for (int idx = lt; idx < G * NF; idx += 256) {
                    int e = idx / NF, f = idx - e * NF;
                    float a = 0.f;
                    if (PB16) {
                        const __nv_bfloat16* pp =
                            (const __nv_bfloat16*)pres + (e * TENC) * NF + f;
#pragma unroll 4
                        for (int ss = 0; ss < TENC; ss++)
                            a += tanha(we[e * 48 + ss] + __bfloat162float(pp[ss * NF])) * vvec[ss];
                    } else {
                        const float* pp = pres + (e * TENC) * NF + f;
#pragma unroll 4
                        for (int ss = 0; ss < TENC; ss++)
                            a += tanha(we[e * 48 + ss] + pp[ss * NF]) * vvec[ss];
                    }
                    sc[e * 132 + f] = a + bb;
                }
            }
            barh();
            warp_softmax(sc + lw * 132, al + lw * 132, NF, lane);
            __syncwarp();
            if (PB16) {
                ipT[lw * KP + 128 + lane]      = xr0 * al[lw * 132 + lane];
                ipT[lw * KP + 128 + lane + 32] = xr1 * al[lw * 132 + lane + 32];
                ipT[lw * KP + 128 + lane + 64] = xr2 * al[lw * 132 + lane + 64];
                ipT[lw * KP + 128 + lane + 96] = xr3 * al[lw * 132 + lane + 96];
                if (lane == 0) ipT[lw * KP + 256] = xr4 * al[lw * 132 + 128];
            } else {
                if (lane < NF) ipT[lw * KP + 128 + lane] = xr0 * al[lw * 132 + lane];
            }
        } else {
            u64 acc0[8], acc1[8];
#pragma unroll
            for (int g = 0; g < 8; g++) { acc0[g] = 0ull; acc1[g] = 0ull; }
            gemm_rows<KP, 64>(W2, 0, ipT, lt, acc0, acc1);
            const int n0 = lt * 2;
            float* pp = pg + n0 * 9;
            float* pq = pg + (n0 + 1) * 9;
#pragma unroll
            for (int g = 0; g < 8; g++) {
                float2 r0 = unpack2(acc0[g]);
                float2 r1 = unpack2(acc1[g]);
                pp[g] = r0.x + r0.y;
                pq[g] = r1.x + r1.y;
            }
        }
        __syncthreads();
        {
            const int half = tid >> 8;
            u64 acc0[8], acc1[8];
#pragma unroll
            for (int g = 0; g < 8; g++) { acc0[g] = 0ull; acc1[g] = 0ull; }
            gemm_rows<KP, XH>(W2, 64 + half * XH, ipT, lt, acc0, acc1);
            const int n0 = lt * 2;
            if (half) {
#pragma unroll
                for (int g = 0; g < 8; g++) {
                    float2 r0 = unpack2(acc0[g]);
                    float2 r1 = unpack2(acc1[g]);
                    gates[g * NG + n0]     = r0.x + r0.y;
                    gates[g * NG + n0 + 1] = r1.x + r1.y;
                }
            }
            __syncthreads();
            if (!half) {
                const float* pp = pg + n0 * 9;
                const float* pq = pg + (n0 + 1) * 9;
                float b0 = bias[n0], b1 = bias[n0 + 1];
#pragma unroll
                for (int g = 0; g < 8; g++) {
                    float2 r0 = unpack2(acc0[g]);
                    float2 r1 = unpack2(acc1[g]);
                    gates[g * NG + n0]     += r0.x + r0.y + pp[g] + b0;
                    gates[g * NG + n0 + 1] += r1.x + r1.y + pq[g] + b1;
                }
            }
        }
        __syncthreads();
#pragma unroll
        for (int u = 0; u < 2; u++) {
            int idx = tid + u * NTH;
            int g = idx >> 7, j = idx & 127;
            float gi = gates[g * NG + j];
            float gf = gates[g * NG + HD + j];
            float gg = gates[g * NG + 2 * HD + j];
            float go = gates[g * NG + 3 * HD + j];
            float c  = hcT[(128 + j) * HCT_STR + g];
            float c2 = siga(gf) * c + siga(gi) * tanha(gg);
            float h  = siga(go) * tanha(c2);
            hcT[j * HCT_STR + g] = h;
            hcT[(128 + j) * HCT_STR + g] = c2;
            ipT[g * KP + j] = h;
            outb[((size_t)(bid * G + g) * TENC + t) * ostride + j] = h;
        }
        __syncthreads();
    }
}

// ---------------- decoder: warp-specialized h-GEMM overlap ----------------
#define D_O_WDT 0
#define D_O_HCT 32768
#define D_O_WD  35328
#define D_O_SC  36352
#define D_O_AL  36736
#define D_O_IP  37120
#define D_O_GT  39168
#define D_O_PG  43264
#define D_O_BS  47872
#define D_O_VV  48384
#define D_O_VR  48520
#define DEC_SMEM_FL 48656

__global__ __launch_bounds__(NTH, 1) void decoder_kernel(
    const float* __restrict__ Vd, const float* __restrict__ Vdb,
    const float* __restrict__ regW, const float* __restrict__ regb,
    float* __restrict__ out) {
    extern __shared__ float sm[];
    float* wdt  = sm + D_O_WDT;
    float* hcT  = sm + D_O_HCT;
    float* wd   = sm + D_O_WD;
    float* score = sm + D_O_SC;
    float* alpha = sm + D_O_AL;
    float* ipT  = sm + D_O_IP;     // [g][KPD]: h 0..127, din 128..255
    float* gates = sm + D_O_GT;
    float* pg   = sm + D_O_PG;     // h-GEMM partials [NG][9]
    float* bias = sm + D_O_BS;
    float* vvec = sm + D_O_VV;
    float* vreg = sm + D_O_VR;
    float* part = gates;           // wd partials: 4 slices x 1024 = gates region

    const int tid = threadIdx.x, bid = blockIdx.x;
    const int lower = (tid < 256);
    const int lt = tid & 255;
    const int lw = lt >> 5, lane = tid & 31;
    const int wid = tid >> 5;

    for (int i = tid; i < 256 * HD; i += NTH) wdt[i] = g_Wdt[i];
    for (int i = tid; i < 256 * HCT_STR; i += NTH) hcT[i] = 0.f;
    for (int i = tid; i < NG; i += NTH) bias[i] = g_bd[i];
    for (int i = tid; i < KPD * G; i += NTH) ipT[i] = 0.f;
    for (int i = tid; i < HD; i += NTH) { vvec[i] = Vd[i]; vreg[i] = regW[i]; }
    if (tid == 0) { vvec[130] = Vdb[0]; vreg[130] = regb[0]; }
    __syncthreads();

    // lower-half mappings
    const int s4 = lt >> 6;             // wd k-slice 0..3
    const int j04 = 2 * (lt & 63);      // wd j-pair
    const int dg = lt >> 5;             // din group (=lw)
    const int dj4 = (lt & 31) * 4;      // din 4 j per thread
    const float* fp = g_fin + ((size_t)(bid * G + dg) * TENC) * HD + dj4;

    for (int sd = 0; sd < DSTEPS; sd++) {
        if (lower) {
            // A: wd projection, 4-way k-split over 256 threads
            {
                u64 a0 = 0, a1 = 0, a2 = 0, a3 = 0, a4 = 0, a5 = 0, a6 = 0, a7 = 0;
                int kb = s4 * 64;
#pragma unroll 8
                for (int kk = 0; kk < 64; kk++) {
                    int k = kb + kk;
                    float2 w = *(const float2*)(wdt + k * HD + j04);
                    u64 w0 = dup2(w.x), w1 = dup2(w.y);
                    const float* hp = hcT + k * HCT_STR;
                    u64 h01 = *(const u64*)(hp);
                    u64 h23 = *(const u64*)(hp + 2);
                    u64 h45 = *(const u64*)(hp + 4);
                    u64 h67 = *(const u64*)(hp + 6);
                    a0 = fma2(w0, h01, a0); a1 = fma2(w0, h23, a1);
                    a2 = fma2(w0, h45, a2); a3 = fma2(w0, h67, a3);
                    a4 = fma2(w1, h01, a4); a5 = fma2(w1, h23, a5);
                    a6 = fma2(w1, h45, a6); a7 = fma2(w1, h67, a7);
                }
                float* pp = part + s4 * 1024 + j04 * 8;
                float2 r;
                r = unpack2(a0); pp[0] = r.x; pp[1] = r.y;
                r = unpack2(a1); pp[2] = r.x; pp[3] = r.y;
                r = unpack2(a2); pp[4] = r.x; pp[5] = r.y;
                r = unpack2(a3); pp[6] = r.x; pp[7] = r.y;
                pp += 8;
                r = unpack2(a4); pp[0] = r.x; pp[1] = r.y;
                r = unpack2(a5); pp[2] = r.x; pp[3] = r.y;
                r = unpack2(a6); pp[4] = r.x; pp[5] = r.y;
                r = unpack2(a7); pp[6] = r.x; pp[7] = r.y;
            }
            barh();
#pragma unroll
            for (int u = 0; u < 4; u++) {
                int o = lt + u * 256;
                float s = part[o] + part[1024 + o] + part[2048 + o] + part[3072 + o];
                int j = o >> 3, g = o & 7;
                wd[g * HD + j] = s;
            }
            barh();
            // B: score, 384 items on 256 threads
#pragma unroll
            for (int u = 0; u < 2; u++) {
                int idx = lt + u * 256;
                if (idx < G * TENC) {
                    int sg = idx / TENC, stt = idx - sg * TENC;
                    const __nv_bfloat16* up =
                        g_udTh + ((size_t)(bid * G + sg) * HD) * TENC + stt;
                    float a = 0.f;
#pragma unroll 4
                    for (int j = 0; j < HD; j++)
                        a += tanha(wd[sg * HD + j] + __bfloat162float(up[(size_t)j * TENC])) * vvec[j];
                    score[sg * TENC + stt] = a + vvec[130];
                }
            }
            barh();
            // softmax (8 warps, one g each) + D: din 4 j/thread
            warp_softmax(score + lw * TENC, alpha + lw * TENC, TENC, lane);
            __syncwarp();
            {
                float a0 = 0.f, a1 = 0.f, a2 = 0.f, a3 = 0.f;
#pragma unroll 4
                for (int tt = 0; tt < TENC; tt++) {
                    float al = alpha[dg * TENC + tt];
                    float4 f4 = *(const float4*)(fp + (size_t)tt * HD);
                    a0 += al * f4.x; a1 += al * f4.y;
                    a2 += al * f4.z; a3 += al * f4.w;
                }
                ipT[dg * KPD + 128 + dj4]     = a0;
                ipT[dg * KPD + 128 + dj4 + 1] = a1;
                ipT[dg * KPD + 128 + dj4 + 2] = a2;
                ipT[dg * KPD + 128 + dj4 + 3] = a3;
            }
        } else {
            // upper 256: h-GEMM rows 0..63 (k 0..127) -> pg partials
            u64 acc0[8], acc1[8];
#pragma unroll
            for (int g = 0; g < 8; g++) { acc0[g] = 0ull; acc1[g] = 0ull; }
            gemm_rows<KPD, 64>(g_W2d, 0, ipT, lt, acc0, acc1);
            const int n0 = lt * 2;
            float* pp = pg + n0 * 9;
            float* pq = pg + (n0 + 1) * 9;
#pragma unroll
            for (int g = 0; g < 8; g++) {
                float2 r0 = unpack2(acc0[g]);
                float2 r1 = unpack2(acc1[g]);
                pp[g] = r0.x + r0.y;
                pq[g] = r1.x + r1.y;
            }
        }
        __syncthreads();
        // din-GEMM: rows 64..127 (k 128..255), 2-way split
        {
            const int half = tid >> 8;
            u64 acc0[8], acc1[8];
#pragma unroll
            for (int g = 0; g < 8; g++) { acc0[g] = 0ull; acc1[g] = 0ull; }
            gemm_rows<KPD, 32>(g_W2d, 64 + half * 32, ipT, lt, acc0, acc1);
            const int n0 = lt * 2;
            if (half) {
#pragma unroll
                for (int g = 0; g < 8; g++) {
                    float2 r0 = unpack2(acc0[g]);
                    float2 r1 = unpack2(acc1[g]);
                    gates[g * NG + n0]     = r0.x + r0.y;
                    gates[g * NG + n0 + 1] = r1.x + r1.y;
                }
            }
            __syncthreads();
            if (!half) {
                const float* pp = pg + n0 * 9;
                const float* pq = pg + (n0 + 1) * 9;
                float b0 = bias[n0], b1 = bias[n0 + 1];
#pragma unroll
                for (int g = 0; g < 8; g++) {
                    float2 r0 = unpack2(acc0[g]);
                    float2 r1 = unpack2(acc1[g]);
                    gates[g * NG + n0]     += r0.x + r0.y + pp[g] + b0;
                    gates[g * NG + n0 + 1] += r1.x + r1.y + pq[g] + b1;
                }
            }
        }
        __syncthreads();
        // F: cell; h -> ipT rows 0..127
#pragma unroll
        for (int u = 0; u < 2; u++) {
            int idx = tid + u * NTH;
            int g = idx >> 7, j = idx & 127;
            float gi = gates[g * NG + j];
            float gf = gates[g * NG + HD + j];
            float gg = gates[g * NG + 2 * HD + j];
            float go = gates[g * NG + 3 * HD + j];
            float c  = hcT[(128 + j) * HCT_STR + g];
            float c2 = siga(gf) * c + siga(gi) * tanha(gg);
            float h  = siga(go) * tanha(c2);
            hcT[j * HCT_STR + g] = h;
            hcT[(128 + j) * HCT_STR + g] = c2;
            ipT[g * KPD + j] = h;
        }
        __syncthreads();
        if (sd >= DSTEPS - TDEC && wid < G) {
            float a = 0.f;
#pragma unroll
            for (int r = 0; r < 4; r++)
                a += hcT[(lane + 32 * r) * HCT_STR + wid] * vreg[lane + 32 * r];
#pragma unroll
            for (int o = 16; o; o >>= 1) a += __shfl_xor_sync(0xffffffffu, a, o);
            if (lane == 0)
                out[(size_t)(bid * G + wid) * TDEC + (sd - (DSTEPS - TDEC))] = a + vreg[130];
        }
    }
}

// ---------------- launch ----------------
extern "C" void kernel_launch(void* const* d_in, const int* in_sizes, int n_in,
                              void* d_out, int out_size) {
    const float* input_p_q = (const float*)d_in[0];
    const float* label_p   = (const float*)d_in[1];
    const float* Ue1_W = (const float*)d_in[2];
    const float* Ue1_b = (const float*)d_in[3];
    const float* We1_W = (const float*)d_in[4];
    const float* Ve1_W = (const float*)d_in[5];
    const float* Ve1_b = (const float*)d_in[6];
    const float* Ue2_W = (const float*)d_in[7];
    const float* Ue2_b = (const float*)d_in[8];
    const float* We2_W = (const float*)d_in[9];
    const float* Ve2_W = (const float*)d_in[10];
    const float* Ve2_b = (const float*)d_in[11];
    const float* Ud_W  = (const float*)d_in[12];
    const float* Ud_b  = (const float*)d_in[13];
    const float* Wd_W  = (const float*)d_in[14];
    const float* Vd_W  = (const float*)d_in[15];
    const float* Vd_b  = (const float*)d_in[16];
    const float* e1_Wih = (const float*)d_in[17];
    const float* e1_Whh = (const float*)d_in[18];
    const float* e1_bih = (const float*)d_in[19];
    const float* e1_bhh = (const float*)d_in[20];
    const float* e2_Wih = (const float*)d_in[21];
    const float* e2_Whh = (const float*)d_in[22];
    const float* e2_bih = (const float*)d_in[23];
    const float* e2_bhh = (const float*)d_in[24];
    const float* d_Wih  = (const float*)d_in[25];
    const float* d_Whh  = (const float*)d_in[26];
    const float* d_bih  = (const float*)d_in[27];
    const float* d_bhh  = (const float*)d_in[28];
    const float* reg_W  = (const float*)d_in[29];
    const float* reg_b  = (const float*)d_in[30];
    float* out = (float*)d_out;

    unsigned *p_W21, *p_W22;
    float *p_Wet1, *p_Wet2;
    float *p_b1, *p_b2, *p_pre1, *p_mid, *p_fin;
    cudaGetSymbolAddress((void**)&p_W21, g_W21);
    cudaGetSymbolAddress((void**)&p_W22, g_W22);
    cudaGetSymbolAddress((void**)&p_Wet1, g_Wet1);
    cudaGetSymbolAddress((void**)&p_Wet2, g_Wet2);
    cudaGetSymbolAddress((void**)&p_b1, g_b1);
    cudaGetSymbolAddress((void**)&p_b2, g_b2);
    cudaGetSymbolAddress((void**)&p_pre1, g_pre1);
    cudaGetSymbolAddress((void**)&p_mid, g_mid);
    cudaGetSymbolAddress((void**)&p_fin, g_fin);

    const int S1_FL = 12288 + (G*TENC*NF1) + (G*TENC*NF1) + 2560 + 384
                      + 1056 + 1056 + KP1 * 8 + 4096 + 4608 + 512 + 136;
    const int S2_FL = 12288 + (G*TENC*NF2/2) + 2560 + 384
                      + 1056 + 1056 + KP2 * 8 + 4096 + 4608 + 512 + 136;
    const int STAGE1_SMEM = S1_FL * 4;
    const int STAGE2_SMEM = S2_FL * 4;
    const int DEC_SMEM    = DEC_SMEM_FL * 4;
    const int UD_SMEM     = (16384 + TENC * 129) * 4;

    cudaFuncSetAttribute((const void*)stage_kernel<KP1, NF1, XH1, false>,
                         cudaFuncAttributeMaxDynamicSharedMemorySize, STAGE1_SMEM);
    cudaFuncSetAttribute((const void*)stage_kernel<KP2, NF2, XH2, true>,
                         cudaFuncAttributeMaxDynamicSharedMemorySize, STAGE2_SMEM);
    cudaFuncSetAttribute((const void*)decoder_kernel,
                         cudaFuncAttributeMaxDynamicSharedMemorySize, DEC_SMEM);
    cudaFuncSetAttribute((const void*)ud_kernel,
                         cudaFuncAttributeMaxDynamicSharedMemorySize, UD_SMEM);

    nop_kernel<<<1, 32>>>();   // keeps ncu capture slot on stage1
    setup_kernel<<<128, 256>>>(e1_Wih, e1_Whh, e2_Wih, e2_Whh, d_Wih, d_Whh,
                               We1_W, We2_W, Wd_W, Ud_W,
                               e1_bih, e1_bhh, e2_bih, e2_bhh, d_bih, d_bhh);
    pre1_kernel<<<BTOT, 256>>>(input_p_q, label_p, Ue1_W, Ue1_b);
    stage_kernel<KP1, NF1, XH1, false><<<NCTA, NTH, STAGE1_SMEM>>>(
        input_p_q, Ve1_W, Ve1_b, p_W21, p_b1, p_Wet1, p_pre1, p_mid, NF2);
    pre2_kernel<<<BTOT, 256>>>(Ue2_W, Ue2_b);
    stage_kernel<KP2, NF2, XH2, true><<<NCTA, NTH, STAGE2_SMEM>>>(
        input_p_q, Ve2_W, Ve2_b, p_W22, p_b2, p_Wet2, nullptr, p_fin, HD);
    ud_kernel<<<BTOT, 256, UD_SMEM>>>(Ud_b);
    decoder_kernel<<<NCTA, NTH, DEC_SMEM>>>(Vd_W, Vd_b, reg_W, reg_b, out);
}

// round 17
// speedup vs baseline: 1.0583x; 1.0583x over previous
#include <cuda_runtime.h>
#include <cuda_bf16.h>

#define TENC 48
#define TDEC 24
#define DSTEPS 30
#define HD 128
#define NF1 17
#define NF2 129
#define KP1 160       // [h(128) | x(17) pad->32]
#define KP2 288       // [h(128) | x(129) pad->160]
#define KPD 256
#define XH1 8         // x u32-rows per half
#define XH2 40
#define G 8
#define NCTA 128
#define NTH 512
#define NG 512
#define BTOT 1024
#define HCT_STR 10

typedef unsigned long long u64;

// ---------------- device scratch (allocation-free) ----------------
__device__ unsigned g_W21[(KP1 / 2) * NG];   // [row][n], row=k-pair, order [h|x]
__device__ unsigned g_W22[(KP2 / 2) * NG];
__device__ unsigned g_W2d[(KPD / 2) * NG];   // decoder: original [din|h] order
__device__ float g_Wet1[256 * TENC];
__device__ float g_Wet2[256 * TENC];
__device__ float g_Wdt[256 * HD];
__device__ float g_Udt[HD * HD];
__device__ float g_b1[NG], g_b2[NG], g_bd[NG];
__device__ float g_pre1[BTOT * TENC * NF1];           // [b][s][f] fp32
__device__ __nv_bfloat16 g_pre2h[BTOT * TENC * NF2];  // [b][s][f] bf16
__device__ float g_mid[BTOT * TENC * NF2];
__device__ float g_fin[BTOT * TENC * HD];
__device__ __nv_bfloat16 g_udTh[BTOT * HD * TENC];

// ---------------- math helpers ----------------
__device__ __forceinline__ float tanha(float x) {
    float y; asm("tanh.approx.f32 %0, %1;" : "=f"(y) : "f"(x)); return y;
}
__device__ __forceinline__ float siga(float x) {
    return fmaf(tanha(0.5f * x), 0.5f, 0.5f);
}
__device__ __forceinline__ u64 fma2(u64 a, u64 b, u64 c) {
    u64 d; asm("fma.rn.f32x2 %0, %1, %2, %3;" : "=l"(d) : "l"(a), "l"(b), "l"(c)); return d;
}
__device__ __forceinline__ u64 dup2(float x) {
    u64 d; unsigned r = __float_as_uint(x);
    asm("mov.b64 %0, {%1, %1};" : "=l"(d) : "r"(r)); return d;
}
__device__ __forceinline__ float2 unpack2(u64 a) {
    unsigned l, h;
    asm("mov.b64 {%0, %1}, %2;" : "=r"(l), "=r"(h) : "l"(a));
    return make_float2(__uint_as_float(l), __uint_as_float(h));
}
__device__ __forceinline__ u64 bf2f2(unsigned w) {
    unsigned lo = w << 16;
    unsigned hi = w & 0xffff0000u;
    u64 d;
    asm("mov.b64 %0, {%1, %2};" : "=l"(d) : "r"(lo), "r"(hi));
    return d;
}
__device__ __forceinline__ void barh() {   // lower-half barrier
    asm volatile("bar.sync 1, 256;" ::: "memory");
}

__device__ __forceinline__ void warp_softmax(const float* score_row, float* alpha_row,
                                             int F, int lane) {
    float mx = -1e30f;
    for (int f = lane; f < F; f += 32) mx = fmaxf(mx, score_row[f]);
#pragma unroll
    for (int o = 16; o; o >>= 1) mx = fmaxf(mx, __shfl_xor_sync(0xffffffffu, mx, o));
    float sm = 0.f;
    for (int f = lane; f < F; f += 32) {
        float e = __expf(score_row[f] - mx);
        alpha_row[f] = e;
        sm += e;
    }
#pragma unroll
    for (int o = 16; o; o >>= 1) sm += __shfl_xor_sync(0xffffffffu, sm, o);
    float inv = __fdividef(1.f, sm);
    for (int f = lane; f < F; f += 32) alpha_row[f] *= inv;
}

__global__ void nop_kernel() {}

// ---- partial gate GEMM over u32-row range [r0, r0+NR): 2 cols/thread ----
// 8-row weight prefetch when NR%8==0 (double MLP); per-accumulator order unchanged.
template <int KP, int NR>
__device__ __forceinline__ void gemm_rows(const unsigned* __restrict__ W2, int r0,
                                          const float* __restrict__ ipT,   // [g][KP]
                                          int lt, u64* acc0, u64* acc1) {
    constexpr int BATCH = (NR % 8 == 0) ? 8 : 4;
    const u64* wp = (const u64*)(W2 + (size_t)r0 * NG) + lt;
    const float* ipb = ipT + 2 * r0;
#pragma unroll 1
    for (int b = 0; b < NR; b += BATCH) {
        u64 w4[BATCH];
#pragma unroll
        for (int i = 0; i < BATCH; i++) w4[i] = wp[(size_t)(b + i) * (NG / 2)];
        u64 wn0[BATCH], wn1[BATCH];
#pragma unroll
        for (int i = 0; i < BATCH; i++) {
            wn0[i] = bf2f2((unsigned)w4[i]);
            wn1[i] = bf2f2((unsigned)(w4[i] >> 32));
        }
#pragma unroll
        for (int i = 0; i < BATCH; i += 4) {
            const float* ipk = ipb + 2 * (b + i);
#pragma unroll
            for (int g = 0; g < 8; g++) {
                const float* r = ipk + g * KP;
                ulonglong2 pA = *(const ulonglong2*)(r);
                ulonglong2 pB = *(const ulonglong2*)(r + 4);
                acc0[g] = fma2(wn0[i + 0], pA.x, acc0[g]);
                acc0[g] = fma2(wn0[i + 1], pA.y, acc0[g]);
                acc0[g] = fma2(wn0[i + 2], pB.x, acc0[g]);
                acc0[g] = fma2(wn0[i + 3], pB.y, acc0[g]);
                acc1[g] = fma2(wn1[i + 0], pA.x, acc1[g]);
                acc1[g] = fma2(wn1[i + 1], pA.y, acc1[g]);
                acc1[g] = fma2(wn1[i + 2], pB.x, acc1[g]);
                acc1[g] = fma2(wn1[i + 3], pB.y, acc1[g]);
            }
        }
    }
}

// ---- decoder gate GEMM (round-12 structure) ----
template <int KP>
__device__ __forceinline__ void gates_gemm5(const unsigned* __restrict__ W2,
                                            const float* __restrict__ bias,
                                            const float* __restrict__ ipT,
                                            float* __restrict__ gates,
                                            float* __restrict__ pg, int tid) {
    constexpr int KKH = KP / 4;
    const int half = tid >> 8;
    const int lt = tid & 255;
    const int n0 = lt * 2;
    const int kk0 = half * KKH;
    u64 acc0[8], acc1[8];
#pragma unroll
    for (int g = 0; g < 8; g++) { acc0[g] = 0ull; acc1[g] = 0ull; }
    gemm_rows<KP, KKH>(W2, kk0, ipT, lt, acc0, acc1);
    if (half) {
        float* pp = pg + n0 * 9;
        float* pq = pg + (n0 + 1) * 9;
#pragma unroll
        for (int g = 0; g < 8; g++) {
            float2 r0 = unpack2(acc0[g]);
            float2 r1 = unpack2(acc1[g]);
            pp[g] = r0.x + r0.y;
            pq[g] = r1.x + r1.y;
        }
    }
    __syncthreads();
    if (!half) {
        const float* pp = pg + n0 * 9;
        const float* pq = pg + (n0 + 1) * 9;
        float b0 = bias[n0], b1 = bias[n0 + 1];
#pragma unroll
        for (int g = 0; g < 8; g++) {
            float2 r0 = unpack2(acc0[g]);
            float2 r1 = unpack2(acc1[g]);
            gates[g * NG + n0]     = r0.x + r0.y + pp[g] + b0;
            gates[g * NG + n0 + 1] = r1.x + r1.y + pq[g] + b1;
        }
    }
}

// ---------------- setup ----------------
__global__ void setup_kernel(
    const float* __restrict__ e1_Wih, const float* __restrict__ e1_Whh,
    const float* __restrict__ e2_Wih, const float* __restrict__ e2_Whh,
    const float* __restrict__ d_Wih,  const float* __restrict__ d_Whh,
    const float* __restrict__ We1,    const float* __restrict__ We2,
    const float* __restrict__ Wd,     const float* __restrict__ Ud,
    const float* __restrict__ e1_bih, const float* __restrict__ e1_bhh,
    const float* __restrict__ e2_bih, const float* __restrict__ e2_bhh,
    const float* __restrict__ d_bih,  const float* __restrict__ d_bhh) {
    int tid = blockIdx.x * blockDim.x + threadIdx.x;
    int nt = gridDim.x * blockDim.x;
    for (int i = tid; i < (KP1 / 2) * NG; i += nt) {
        int kk = i / NG, n = i % NG;
        float v[2];
#pragma unroll
        for (int q = 0; q < 2; q++) {
            int k = 2 * kk + q;
            if (k < HD) v[q] = e1_Whh[n * HD + k];
            else if (k - HD < NF1) v[q] = e1_Wih[n * NF1 + (k - HD)];
            else v[q] = 0.f;
        }
        g_W21[i] = (unsigned)__bfloat16_as_ushort(__float2bfloat16(v[0]))
                 | ((unsigned)__bfloat16_as_ushort(__float2bfloat16(v[1])) << 16);
    }
    for (int i = tid; i < (KP2 / 2) * NG; i += nt) {
        int kk = i / NG, n = i % NG;
        float v[2];
#pragma unroll
        for (int q = 0; q < 2; q++) {
            int k = 2 * kk + q;
            if (k < HD) v[q] = e2_Whh[n * HD + k];
            else if (k - HD < NF2) v[q] = e2_Wih[n * NF2 + (k - HD)];
            else v[q] = 0.f;
        }
        g_W22[i] = (unsigned)__bfloat16_as_ushort(__float2bfloat16(v[0]))
                 | ((unsigned)__bfloat16_as_ushort(__float2bfloat16(v[1])) << 16);
    }
    for (int i = tid; i < (KPD / 2) * NG; i += nt) {
        int kk = i / NG, n = i % NG;
        int k0 = 2 * kk, k1 = 2 * kk + 1;
        float v0 = (k0 < HD) ? d_Wih[n * HD + k0] : d_Whh[n * HD + (k0 - HD)];
        float v1 = (k1 < HD) ? d_Wih[n * HD + k1] : d_Whh[n * HD + (k1 - HD)];
        g_W2d[i] = (unsigned)__bfloat16_as_ushort(__float2bfloat16(v0))
                 | ((unsigned)__bfloat16_as_ushort(__float2bfloat16(v1)) << 16);
    }
    for (int i = tid; i < 256 * TENC; i += nt) {
        int k = i / TENC, ss = i % TENC;
        g_Wet1[i] = We1[ss * 256 + k];
        g_Wet2[i] = We2[ss * 256 + k];
    }
    for (int i = tid; i < 256 * HD; i += nt) {
        int k = i / HD, j = i % HD;
        g_Wdt[i] = Wd[j * 256 + k];
    }
    for (int i = tid; i < HD * HD; i += nt) {
        int k = i / HD, j = i % HD;
        g_Udt[i] = Ud[j * HD + k];
    }
    for (int i = tid; i < NG; i += nt) {
        g_b1[i] = e1_bih[i] + e1_bhh[i];
        g_b2[i] = e2_bih[i] + e2_bhh[i];
        g_bd[i] = d_bih[i] + d_bhh[i];
    }
}

// ---------------- pre1 ----------------
__global__ __launch_bounds__(256) void pre1_kernel(
    const float* __restrict__ inp, const float* __restrict__ lab,
    const float* __restrict__ Ue1, const float* __restrict__ Ue1b) {
    __shared__ float xs[TENC * NF1];
    __shared__ float ue[TENC * TENC];
    int b = blockIdx.x, tid = threadIdx.x;
    for (int i = tid; i < TENC * NF1; i += 256) {
        int t = i / NF1, f = i % NF1;
        xs[i] = inp[((size_t)b * TENC + t) * 18 + f + 1];
    }
    for (int i = tid; i < TENC * TENC; i += 256) ue[i] = Ue1[i];
    for (int i = tid; i < TENC; i += 256)
        g_mid[((size_t)b * TENC + i) * NF2 + HD] = lab[(size_t)b * TENC + i];
    __syncthreads();
    for (int i = tid; i < TENC * NF1; i += 256) {
        int ss = i / NF1, f = i % NF1;
        float a = 0.f;
#pragma unroll 8
        for (int t = 0; t < TENC; t++) a += xs[t * NF1 + f] * ue[ss * TENC + t];
        g_pre1[(size_t)b * TENC * NF1 + i] = a + Ue1b[ss];
    }
}

// ---------------- pre2 (bf16 out) ----------------
__global__ __launch_bounds__(256) void pre2_kernel(
    const float* __restrict__ Ue2, const float* __restrict__ Ue2b) {
    __shared__ float ms[TENC * 130];
    __shared__ float ue[TENC * TENC];
    int b = blockIdx.x, tid = threadIdx.x;
    for (int i = tid; i < TENC * NF2; i += 256) {
        int t = i / NF2, f = i % NF2;
        ms[t * 130 + f] = g_mid[(size_t)b * TENC * NF2 + i];
    }
    for (int i = tid; i < TENC; i += 256) ms[i * 130 + 129] = 0.f;
    for (int i = tid; i < TENC * TENC; i += 256) ue[i] = Ue2[i];
    __syncthreads();
    for (int u = tid; u < TENC * 65; u += 256) {
        int ss = u / 65, q = u % 65;
        int f0 = 2 * q;
        u64 acc = 0ull;
#pragma unroll 8
        for (int t = 0; t < TENC; t++)
            acc = fma2(dup2(ue[ss * TENC + t]), *(const u64*)(ms + t * 130 + f0), acc);
        float2 r = unpack2(acc);
        float bb = Ue2b[ss];
        size_t base = (size_t)b * TENC * NF2 + ss * NF2;
        g_pre2h[base + f0] = __float2bfloat16(r.x + bb);
        if (f0 < 128) g_pre2h[base + f0 + 1] = __float2bfloat16(r.y + bb);
    }
}

// ---------------- ud (bf16 out, transposed) ----------------
__global__ __launch_bounds__(256) void ud_kernel(const float* __restrict__ Udb) {
    extern __shared__ float sm_ud[];
    float* udt = sm_ud;
    float* fs  = sm_ud + 16384;
    int b = blockIdx.x, tid = threadIdx.x;
    for (int i = tid; i < HD * HD; i += 256) udt[i] = g_Udt[i];
    for (int i = tid; i < TENC * HD; i += 256) {
        int t = i >> 7, k = i & 127;
        fs[t * 129 + k] = g_fin[(size_t)b * TENC * HD + i];
    }
    __syncthreads();
    for (int u = tid; u < 32 * TENC; u += 256) {
        int t = u % TENC, jq = u / TENC;
        int j0 = 4 * jq;
        float a0 = Udb[j0], a1 = Udb[j0 + 1], a2 = Udb[j0 + 2], a3 = Udb[j0 + 3];
#pragma unroll 8
        for (int k = 0; k < HD; k++) {
            float f = fs[t * 129 + k];
            float4 uu = *(const float4*)(udt + k * HD + j0);
            a0 += f * uu.x; a1 += f * uu.y; a2 += f * uu.z; a3 += f * uu.w;
        }
        size_t base = (size_t)b * HD * TENC;
        g_udTh[base + (size_t)(j0 + 0) * TENC + t] = __float2bfloat16(a0);
        g_udTh[base + (size_t)(j0 + 1) * TENC + t] = __float2bfloat16(a1);
        g_udTh[base + (size_t)(j0 + 2) * TENC + t] = __float2bfloat16(a2);
        g_udTh[base + (size_t)(j0 + 3) * TENC + t] = __float2bfloat16(a3);
    }
}

// ---------------- encoder stage: warp-specialized h-GEMM overlap ----------------
template <int KP, int NF, int XH, bool PB16>
__global__ __launch_bounds__(NTH, 1) void stage_kernel(
    const float* __restrict__ inp,
    const float* __restrict__ Ve, const float* __restrict__ Veb,
    const unsigned* __restrict__ W2, const float* __restrict__ bsum,
    const float* __restrict__ Wet, const float* __restrict__ preF,
    float* __restrict__ outb, int ostride) {
    extern __shared__ float sm[];
    constexpr int PRE_FL = PB16 ? (G * TENC * NF / 2) : (G * TENC * NF);
    constexpr int XS_FL  = PB16 ? 0 : (G * TENC * NF1);
    constexpr int O_PRE = 12288;
    constexpr int O_XS  = O_PRE + PRE_FL;
    constexpr int O_HCT = O_XS + XS_FL;
    constexpr int O_WE  = O_HCT + 256 * HCT_STR;
    constexpr int O_SC  = O_WE + 384;
    constexpr int O_AL  = O_SC + 1056;
    constexpr int O_IP  = O_AL + 1056;
    constexpr int O_GT  = O_IP + KP * 8;
    constexpr int O_PG  = O_GT + 4096;
    constexpr int O_BS  = O_PG + 4608;
    constexpr int O_VV  = O_BS + 512;

    float* wet  = sm;
    float* pres = sm + O_PRE;
    float* xs   = sm + O_XS;
    float* hcT  = sm + O_HCT;
    float* we   = sm + O_WE;
    float* sc   = sm + O_SC;
    float* al   = sm + O_AL;
    float* ipT  = sm + O_IP;
    float* gates = sm + O_GT;
    float* pg   = sm + O_PG;
    float* bias = sm + O_BS;
    float* vvec = sm + O_VV;

    const int tid = threadIdx.x, bid = blockIdx.x;
    const int lower = (tid < 256);
    const int lt = tid & 255;
    const int lw = lt >> 5;
    const int lane = tid & 31;

    for (int i = tid; i < 256 * TENC; i += NTH) wet[i] = Wet[i];
    if (PB16) {
        const unsigned* src = (const unsigned*)(g_pre2h + (size_t)bid * G * TENC * NF2);
        unsigned* dst = (unsigned*)pres;
        for (int i = tid; i < G * TENC * NF2 / 2; i += NTH) dst[i] = src[i];
    } else {
        const float* src = preF + (size_t)bid * G * TENC * NF;
        for (int i = tid; i < G * TENC * NF; i += NTH) pres[i] = src[i];
        for (int i = tid; i < G * TENC * NF1; i += NTH) {
            int g = i / (TENC * NF1);
            int r = i - g * TENC * NF1;
            int t = r / NF1, f = r - t * NF1;
            xs[i] = inp[((size_t)(bid * G + g) * TENC + t) * 18 + f + 1];
        }
    }
    for (int i = tid; i < 256 * HCT_STR; i += NTH) hcT[i] = 0.f;
    for (int i = tid; i < NG; i += NTH) bias[i] = bsum[i];
    for (int i = tid; i < TENC; i += NTH) vvec[i] = Ve[i];
    if (tid == 0) vvec[130] = Veb[0];
    for (int i = tid; i < KP * 8; i += NTH) ipT[i] = 0.f;
    __syncthreads();

    const int ae = lt / 24;
    const int ass0 = 2 * (lt % 24);

    for (int t = 0; t < TENC; t++) {
        if (lower) {
            float xr0 = 0.f, xr1 = 0.f, xr2 = 0.f, xr3 = 0.f, xr4 = 0.f;
            if (PB16) {
                const float* xp = g_mid + ((size_t)(bid * G + lw) * TENC + t) * NF2;
                xr0 = xp[lane]; xr1 = xp[lane + 32];
                xr2 = xp[lane + 64]; xr3 = xp[lane + 96];
                if (lane == 0) xr4 = xp[128];
            } else {
                if (lane < NF) xr0 = xs[lw * TENC * NF1 + t * NF1 + lane];
            }
            if (lt < 192) {
                u64 acc0 = 0ull, acc1 = 0ull;
#pragma unroll 4
                for (int kk = 0; kk < 128; kk++) {
                    u64 w0 = *(const u64*)(wet + kk * TENC + ass0);
                    u64 w1 = *(const u64*)(wet + (kk + 128) * TENC + ass0);
                    acc0 = fma2(w0, dup2(hcT[kk * HCT_STR + ae]), acc0);
                    acc1 = fma2(w1, dup2(hcT[(kk + 128) * HCT_STR + ae]), acc1);
                }
                float2 v0 = unpack2(acc0);
                float2 v1 = unpack2(acc1);
                we[ae * 48 + ass0]     = v0.x + v1.x;
                we[ae * 48 + ass0 + 1] = v0.y + v1.y;
            }
            barh();
            {
                float bb = vvec[130];
                for (int idx = lt; idx < G * NF; idx += 256) {
                    int e = idx / NF, f = idx - e * NF;
                    float a = 0.f;
                    if (PB16) {
                        const __nv_bfloat16* pp =
                            (const __nv_bfloat16*)pres + (e * TENC) * NF + f;
#pragma unroll 4
                        for (int ss = 0; ss < TENC; ss++)
                            a += tanha(we[e * 48 + ss] + __bfloat162float(pp[ss * NF])) * vvec[ss];
                    } else {
                        const float* pp = pres + (e * TENC) * NF + f;
#pragma unroll 4
                        for (int ss = 0; ss < TENC; ss++)
                            a += tanha(we[e * 48 + ss] + pp[ss * NF]) * vvec[ss];
                    }
                    sc[e * 132 + f] = a + bb;
                }
            }
            barh();
            warp_softmax(sc + lw * 132, al + lw * 132, NF, lane);
            __syncwarp();
            if (PB16) {
                ipT[lw * KP + 128 + lane]      = xr0 * al[lw * 132 + lane];
                ipT[lw * KP + 128 + lane + 32] = xr1 * al[lw * 132 + lane + 32];
                ipT[lw * KP + 128 + lane + 64] = xr2 * al[lw * 132 + lane + 64];
                ipT[lw * KP + 128 + lane + 96] = xr3 * al[lw * 132 + lane + 96];
                if (lane == 0) ipT[lw * KP + 256] = xr4 * al[lw * 132 + 128];
            } else {
                if (lane < NF) ipT[lw * KP + 128 + lane] = xr0 * al[lw * 132 + lane];
            }
        } else {
            u64 acc0[8], acc1[8];
#pragma unroll
            for (int g = 0; g < 8; g++) { acc0[g] = 0ull; acc1[g] = 0ull; }
            gemm_rows<KP, 64>(W2, 0, ipT, lt, acc0, acc1);
            const int n0 = lt * 2;
            float* pp = pg + n0 * 9;
            float* pq = pg + (n0 + 1) * 9;
#pragma unroll
            for (int g = 0; g < 8; g++) {
                float2 r0 = unpack2(acc0[g]);
                float2 r1 = unpack2(acc1[g]);
                pp[g] = r0.x + r0.y;
                pq[g] = r1.x + r1.y;
            }
        }
        __syncthreads();
        {
            const int half = tid >> 8;
            u64 acc0[8], acc1[8];
#pragma unroll
            for (int g = 0; g < 8; g++) { acc0[g] = 0ull; acc1[g] = 0ull; }
            gemm_rows<KP, XH>(W2, 64 + half * XH, ipT, lt, acc0, acc1);
            const int n0 = lt * 2;
            if (half) {
#pragma unroll
                for (int g = 0; g < 8; g++) {
                    float2 r0 = unpack2(acc0[g]);
                    float2 r1 = unpack2(acc1[g]);
                    gates[g * NG + n0]     = r0.x + r0.y;
                    gates[g * NG + n0 + 1] = r1.x + r1.y;
                }
            }
            __syncthreads();
            if (!half) {
                const float* pp = pg + n0 * 9;
                const float* pq = pg + (n0 + 1) * 9;
                float b0 = bias[n0], b1 = bias[n0 + 1];
#pragma unroll
                for (int g = 0; g < 8; g++) {
                    float2 r0 = unpack2(acc0[g]);
                    float2 r1 = unpack2(acc1[g]);
                    gates[g * NG + n0]     += r0.x + r0.y + pp[g] + b0;
                    gates[g * NG + n0 + 1] += r1.x + r1.y + pq[g] + b1;
                }
            }
        }
        __syncthreads();
#pragma unroll
        for (int u = 0; u < 2; u++) {
            int idx = tid + u * NTH;
            int g = idx >> 7, j = idx & 127;
            float gi = gates[g * NG + j];
            float gf = gates[g * NG + HD + j];
            float gg = gates[g * NG + 2 * HD + j];
            float go = gates[g * NG + 3 * HD + j];
            float c  = hcT[(128 + j) * HCT_STR + g];
            float c2 = siga(gf) * c + siga(gi) * tanha(gg);
            float h  = siga(go) * tanha(c2);
            hcT[j * HCT_STR + g] = h;
            hcT[(128 + j) * HCT_STR + g] = c2;
            ipT[g * KP + j] = h;
            outb[((size_t)(bid * G + g) * TENC + t) * ostride + j] = h;
        }
        __syncthreads();
    }
}

// ---------------- decoder (round-12 structure) ----------------
#define D_O_WDT 0
#define D_O_HCT 32768
#define D_O_WD  35328
#define D_O_SC  36352
#define D_O_AL  36736
#define D_O_IP  37120
#define D_O_GT  39168
#define D_O_PG  43264
#define D_O_BS  47872
#define D_O_VV  48384
#define D_O_VR  48520
#define DEC_SMEM_FL 48656

__global__ __launch_bounds__(NTH, 1) void decoder_kernel(
    const float* __restrict__ Vd, const float* __restrict__ Vdb,
    const float* __restrict__ regW, const float* __restrict__ regb,
    float* __restrict__ out) {
    extern __shared__ float sm[];
    float* wdt  = sm + D_O_WDT;
    float* hcT  = sm + D_O_HCT;
    float* wd   = sm + D_O_WD;
    float* score = sm + D_O_SC;
    float* alpha = sm + D_O_AL;
    float* ipT  = sm + D_O_IP;
    float* gates = sm + D_O_GT;
    float* pg   = sm + D_O_PG;
    float* bias = sm + D_O_BS;
    float* vvec = sm + D_O_VV;
    float* vreg = sm + D_O_VR;
    float* part = gates;

    const int tid = threadIdx.x, bid = blockIdx.x;
    const int wid = tid >> 5, lane = tid & 31;

    for (int i = tid; i < 256 * HD; i += NTH) wdt[i] = g_Wdt[i];
    for (int i = tid; i < 256 * HCT_STR; i += NTH) hcT[i] = 0.f;
    for (int i = tid; i < NG; i += NTH) bias[i] = g_bd[i];
    for (int i = tid; i < KPD * G; i += NTH) ipT[i] = 0.f;
    for (int i = tid; i < HD; i += NTH) { vvec[i] = Vd[i]; vreg[i] = regW[i]; }
    if (tid == 0) { vvec[130] = Vdb[0]; vreg[130] = regb[0]; }
    __syncthreads();

    bool sval = tid < G * TENC;
    int sg = sval ? tid / TENC : 0, stt = sval ? tid % TENC : 0;
    const __nv_bfloat16* up = g_udTh + ((size_t)(bid * G + sg) * HD) * TENC + stt;
    int dg = tid >> 6, dj = (tid & 63) * 2;
    const float* fp = g_fin + ((size_t)(bid * G + dg) * TENC) * HD + dj;
    const int s8 = tid >> 6;
    const int jp = tid & 63, j0 = 2 * jp;

    for (int sd = 0; sd < DSTEPS; sd++) {
        {
            u64 a0 = 0, a1 = 0, a2 = 0, a3 = 0, a4 = 0, a5 = 0, a6 = 0, a7 = 0;
            int kb = s8 * 32;
#pragma unroll 8
            for (int kk = 0; kk < 32; kk++) {
                int k = kb + kk;
                float2 w = *(const float2*)(wdt + k * HD + j0);
                u64 w0 = dup2(w.x), w1 = dup2(w.y);
                const float* hp = hcT + k * HCT_STR;
                u64 h01 = *(const u64*)(hp);
                u64 h23 = *(const u64*)(hp + 2);
                u64 h45 = *(const u64*)(hp + 4);
                u64 h67 = *(const u64*)(hp + 6);
                a0 = fma2(w0, h01, a0); a1 = fma2(w0, h23, a1);
                a2 = fma2(w0, h45, a2); a3 = fma2(w0, h67, a3);
                a4 = fma2(w1, h01, a4); a5 = fma2(w1, h23, a5);
                a6 = fma2(w1, h45, a6); a7 = fma2(w1, h67, a7);
            }
            float* pp = part + s8 * 1024 + j0 * 8;
            float2 r;
            r = unpack2(a0); pp[0] = r.x; pp[1] = r.y;
            r = unpack2(a1); pp[2] = r.x; pp[3] = r.y;
            r = unpack2(a2); pp[4] = r.x; pp[5] = r.y;
            r = unpack2(a3); pp[6] = r.x; pp[7] = r.y;
            pp += 8;
            r = unpack2(a4); pp[0] = r.x; pp[1] = r.y;
            r = unpack2(a5); pp[2] = r.x; pp[3] = r.y;
            r = unpack2(a6); pp[4] = r.x; pp[5] = r.y;
            r = unpack2(a7); pp[6] = r.x; pp[7] = r.y;
        }
        __syncthreads();
#pragma unroll
        for (int u = 0; u < 2; u++) {
            int o = tid + u * NTH;
            float s = 0.f;
#pragma unroll
            for (int q = 0; q < 8; q++) s += part[q * 1024 + o];
            int j = o >> 3, g = o & 7;
            wd[g * HD + j] = s;
        }
        __syncthreads();
        {
            float a = 0.f;
#pragma unroll 4
            for (int j = 0; j < HD; j++)
                a += tanha(wd[sg * HD + j] + __bfloat162float(up[(size_t)j * TENC])) * vvec[j];
            if (sval) score[sg * TENC + stt] = a + vvec[130];
        }
        __syncthreads();
        if (wid < G) warp_softmax(score + wid * TENC, alpha + wid * TENC, TENC, lane);
        __syncthreads();
        {
            float a0 = 0.f, a1 = 0.f;
#pragma unroll 4
            for (int tt = 0; tt < TENC; tt++) {
                float al = alpha[dg * TENC + tt];
                float2 f2 = *(const float2*)(fp + (size_t)tt * HD);
                a0 += al * f2.x; a1 += al * f2.y;
            }
            ipT[dg * KPD + dj] = a0;
            ipT[dg * KPD + dj + 1] = a1;
        }
        __syncthreads();
        gates_gemm5<KPD>(g_W2d, bias, ipT, gates, pg, tid);
        __syncthreads();
        for (int idx = tid; idx < G * HD; idx += NTH) {
            int g = idx >> 7, j = idx & 127;
            float gi = gates[g * NG + j];
            float gf = gates[g * NG + HD + j];
            float gg = gates[g * NG + 2 * HD + j];
            float go = gates[g * NG + 3 * HD + j];
            float c  = hcT[(128 + j) * HCT_STR + g];
            float c2 = siga(gf) * c + siga(gi) * tanha(gg);
            float h  = siga(go) * tanha(c2);
            hcT[j * HCT_STR + g] = h;
            hcT[(128 + j) * HCT_STR + g] = c2;
            ipT[g * KPD + HD + j] = h;
        }
        __syncthreads();
        if (sd >= DSTEPS - TDEC && wid < G) {
            float a = 0.f;
#pragma unroll
            for (int r = 0; r < 4; r++)
                a += hcT[(lane + 32 * r) * HCT_STR + wid] * vreg[lane + 32 * r];
#pragma unroll
            for (int o = 16; o; o >>= 1) a += __shfl_xor_sync(0xffffffffu, a, o);
            if (lane == 0)
                out[(size_t)(bid * G + wid) * TDEC + (sd - (DSTEPS - TDEC))] = a + vreg[130];
        }
    }
}

// ---------------- launch ----------------
extern "C" void kernel_launch(void* const* d_in, const int* in_sizes, int n_in,
                              void* d_out, int out_size) {
    const float* input_p_q = (const float*)d_in[0];
    const float* label_p   = (const float*)d_in[1];
    const float* Ue1_W = (const float*)d_in[2];
    const float* Ue1_b = (const float*)d_in[3];
    const float* We1_W = (const float*)d_in[4];
    const float* Ve1_W = (const float*)d_in[5];
    const float* Ve1_b = (const float*)d_in[6];
    const float* Ue2_W = (const float*)d_in[7];
    const float* Ue2_b = (const float*)d_in[8];
    const float* We2_W = (const float*)d_in[9];
    const float* Ve2_W = (const float*)d_in[10];
    const float* Ve2_b = (const float*)d_in[11];
    const float* Ud_W  = (const float*)d_in[12];
    const float* Ud_b  = (const float*)d_in[13];
    const float* Wd_W  = (const float*)d_in[14];
    const float* Vd_W  = (const float*)d_in[15];
    const float* Vd_b  = (const float*)d_in[16];
    const float* e1_Wih = (const float*)d_in[17];
    const float* e1_Whh = (const float*)d_in[18];
    const float* e1_bih = (const float*)d_in[19];
    const float* e1_bhh = (const float*)d_in[20];
    const float* e2_Wih = (const float*)d_in[21];
    const float* e2_Whh = (const float*)d_in[22];
    const float* e2_bih = (const float*)d_in[23];
    const float* e2_bhh = (const float*)d_in[24];
    const float* d_Wih  = (const float*)d_in[25];
    const float* d_Whh  = (const float*)d_in[26];
    const float* d_bih  = (const float*)d_in[27];
    const float* d_bhh  = (const float*)d_in[28];
    const float* reg_W  = (const float*)d_in[29];
    const float* reg_b  = (const float*)d_in[30];
    float* out = (float*)d_out;

    unsigned *p_W21, *p_W22;
    float *p_Wet1, *p_Wet2;
    float *p_b1, *p_b2, *p_pre1, *p_mid, *p_fin;
    cudaGetSymbolAddress((void**)&p_W21, g_W21);
    cudaGetSymbolAddress((void**)&p_W22, g_W22);
    cudaGetSymbolAddress((void**)&p_Wet1, g_Wet1);
    cudaGetSymbolAddress((void**)&p_Wet2, g_Wet2);
    cudaGetSymbolAddress((void**)&p_b1, g_b1);
    cudaGetSymbolAddress((void**)&p_b2, g_b2);
    cudaGetSymbolAddress((void**)&p_pre1, g_pre1);
    cudaGetSymbolAddress((void**)&p_mid, g_mid);
    cudaGetSymbolAddress((void**)&p_fin, g_fin);

    const int S1_FL = 12288 + (G*TENC*NF1) + (G*TENC*NF1) + 2560 + 384
                      + 1056 + 1056 + KP1 * 8 + 4096 + 4608 + 512 + 136;
    const int S2_FL = 12288 + (G*TENC*NF2/2) + 2560 + 384
                      + 1056 + 1056 + KP2 * 8 + 4096 + 4608 + 512 + 136;
    const int STAGE1_SMEM = S1_FL * 4;
    const int STAGE2_SMEM = S2_FL * 4;
    const int DEC_SMEM    = DEC_SMEM_FL * 4;
    const int UD_SMEM     = (16384 + TENC * 129) * 4;

    cudaFuncSetAttribute((const void*)stage_kernel<KP1, NF1, XH1, false>,
                         cudaFuncAttributeMaxDynamicSharedMemorySize, STAGE1_SMEM);
    cudaFuncSetAttribute((const void*)stage_kernel<KP2, NF2, XH2, true>,
                         cudaFuncAttributeMaxDynamicSharedMemorySize, STAGE2_SMEM);
    cudaFuncSetAttribute((const void*)decoder_kernel,
                         cudaFuncAttributeMaxDynamicSharedMemorySize, DEC_SMEM);
    cudaFuncSetAttribute((const void*)ud_kernel,
                         cudaFuncAttributeMaxDynamicSharedMemorySize, UD_SMEM);

    nop_kernel<<<1, 32>>>();   // keeps ncu capture slot on stage1
    setup_kernel<<<128, 256>>>(e1_Wih, e1_Whh, e2_Wih, e2_Whh, d_Wih, d_Whh,
                               We1_W, We2_W, Wd_W, Ud_W,
                               e1_bih, e1_bhh, e2_bih, e2_bhh, d_bih, d_bhh);
    pre1_kernel<<<BTOT, 256>>>(input_p_q, label_p, Ue1_W, Ue1_b);
    stage_kernel<KP1, NF1, XH1, false><<<NCTA, NTH, STAGE1_SMEM>>>(
        input_p_q, Ve1_W, Ve1_b, p_W21, p_b1, p_Wet1, p_pre1, p_mid, NF2);
    pre2_kernel<<<BTOT, 256>>>(Ue2_W, Ue2_b);
    stage_kernel<KP2, NF2, XH2, true><<<NCTA, NTH, STAGE2_SMEM>>>(
        input_p_q, Ve2_W, Ve2_b, p_W22, p_b2, p_Wet2, nullptr, p_fin, HD);
    ud_kernel<<<BTOT, 256, UD_SMEM>>>(Ud_b);
    decoder_kernel<<<NCTA, NTH, DEC_SMEM>>>(Vd_W, Vd_b, reg_W, reg_b, out);
}